// round 1
// baseline (speedup 1.0000x reference)
#include <cuda_runtime.h>
#include <cuda_bf16.h>
#include <math.h>

#define NN 20000
#define EE 320000
#define ET (EE + NN)       // 340000 edges incl self loops
#define FIN 128
#define F2C 64
#define HC 8
#define D1 512             // H*F2
#define G4 256             // 4*F2

// ---------------- scratch (device globals; no allocation allowed) ------------
__device__ float g_h1[NN * D1];        // x @ W1
__device__ float g_agg1[NN * D1];      // GAT1 output
__device__ float g_gates[NN * G4];     // LSTM gates
__device__ float g_h2[NN * F2C];       // LSTM out (relu'd)
__device__ float g_h3[NN * D1];        // h2 @ W2
__device__ float g_agg2[NN * D1];      // GAT2 output (pre-softmax)
__device__ float g_as[NN * HC];
__device__ float g_ad[NN * HC];
__device__ float g_m[NN * HC];
__device__ float g_den[NN * HC];
__device__ float g_Wiht[D1 * G4];      // W_ih transposed -> [512,256]
__device__ int   g_deg[NN];
__device__ int   g_offs[NN + 1];
__device__ int   g_cur[NN];
__device__ int   g_csrc[ET];

__device__ __forceinline__ float sigf(float x) { return 1.0f / (1.0f + __expf(-x)); }

// ---------------- CSR build -------------------------------------------------
__global__ void k_degree(const int* __restrict__ ei, int E) {
    int i = blockIdx.x * blockDim.x + threadIdx.x;
    if (i >= E + NN) return;
    int dst = (i < E) ? ei[E + i] : (i - E);
    atomicAdd(&g_deg[dst], 1);
}

__global__ void k_scan() {
    __shared__ int sums[1024];
    const int CH = 20;                       // 1024*20 = 20480 >= NN
    int t = threadIdx.x;
    int b = t * CH;
    int e = min(b + CH, NN);
    int tmp[CH];
    int local = 0;
    for (int i = b; i < e; i++) { tmp[i - b] = g_deg[i]; local += tmp[i - b]; }
    sums[t] = local;
    __syncthreads();
    for (int o = 1; o < 1024; o <<= 1) {
        int v = (t >= o) ? sums[t - o] : 0;
        __syncthreads();
        sums[t] += v;
        __syncthreads();
    }
    int run = sums[t] - local;               // exclusive prefix
    for (int i = b; i < e; i++) {
        g_offs[i] = run;
        g_cur[i]  = run;
        run += tmp[i - b];
    }
    if (b < NN && e == NN) g_offs[NN] = run;
}

__global__ void k_scatter(const int* __restrict__ ei, int E) {
    int i = blockIdx.x * blockDim.x + threadIdx.x;
    if (i >= E + NN) return;
    int src, dst;
    if (i < E) { src = ei[i]; dst = ei[E + i]; }
    else       { src = dst = i - E; }
    int pos = atomicAdd(&g_cur[dst], 1);
    g_csrc[pos] = src;
}

// ---------------- W_ih transpose --------------------------------------------
__global__ void k_transpose(const float* __restrict__ Wih) {
    int idx = blockIdx.x * blockDim.x + threadIdx.x;
    if (idx >= G4 * D1) return;
    int j = idx >> 9;          // 0..255
    int k = idx & 511;         // 0..511
    g_Wiht[k * G4 + j] = Wih[idx];
}

// ---------------- SGEMM: C[M,N] = A[M,K] @ B[K,N], row-major -----------------
#define BM 128
#define BN 128
#define BK 8
#define TM 8
#define TN 8
__global__ __launch_bounds__(256) void k_sgemm(int M, int N, int K,
                                               const float* __restrict__ A,
                                               const float* __restrict__ B,
                                               float* __restrict__ C) {
    __shared__ float As[BK][BM];
    __shared__ float Bs[BK][BN];
    int cRow = blockIdx.y, cCol = blockIdx.x;
    int tid = threadIdx.x;
    int threadRow = tid / (BN / TN);         // 0..15
    int threadCol = tid % (BN / TN);         // 0..15
    int innerRowA = tid / 2;                 // 0..127
    int innerColA = tid % 2;                 // *4 -> col in [0,8)
    int innerRowB = tid / 32;                // 0..7
    int innerColB = tid % 32;                // *4

    const float* Ap = A + (long)cRow * BM * K;
    const float* Bp = B + cCol * BN;
    float acc[TM][TN];
#pragma unroll
    for (int i = 0; i < TM; i++)
#pragma unroll
        for (int j = 0; j < TN; j++) acc[i][j] = 0.0f;

    float regM[TM], regN[TN];
    for (int k0 = 0; k0 < K; k0 += BK) {
        float4 a = make_float4(0.f, 0.f, 0.f, 0.f);
        int gr = cRow * BM + innerRowA;
        if (gr < M) a = *(const float4*)&Ap[innerRowA * K + innerColA * 4];
        As[innerColA * 4 + 0][innerRowA] = a.x;
        As[innerColA * 4 + 1][innerRowA] = a.y;
        As[innerColA * 4 + 2][innerRowA] = a.z;
        As[innerColA * 4 + 3][innerRowA] = a.w;
        float4 bv = *(const float4*)&Bp[innerRowB * N + innerColB * 4];
        *(float4*)&Bs[innerRowB][innerColB * 4] = bv;
        __syncthreads();
        Ap += BK;
        Bp += (long)BK * N;
#pragma unroll
        for (int k = 0; k < BK; k++) {
#pragma unroll
            for (int i = 0; i < TM; i++) regM[i] = As[k][threadRow * TM + i];
#pragma unroll
            for (int j = 0; j < TN; j++) regN[j] = Bs[k][threadCol * TN + j];
#pragma unroll
            for (int i = 0; i < TM; i++)
#pragma unroll
                for (int j = 0; j < TN; j++) acc[i][j] += regM[i] * regN[j];
        }
        __syncthreads();
    }
    float* Cp = C + (long)cRow * BM * N + cCol * BN;
#pragma unroll
    for (int i = 0; i < TM; i++) {
        int gr = cRow * BM + threadRow * TM + i;
        if (gr >= M) break;
        float* crow = Cp + (long)(threadRow * TM + i) * N + threadCol * TN;
        *(float4*)&crow[0] = make_float4(acc[i][0], acc[i][1], acc[i][2], acc[i][3]);
        *(float4*)&crow[4] = make_float4(acc[i][4], acc[i][5], acc[i][6], acc[i][7]);
    }
}

// ---------------- attention dots: a_s[n,h], a_d[n,h] -------------------------
// one block per node, warp w handles head w
__global__ void k_attn(const float* __restrict__ hmat,
                       const float* __restrict__ asrc,
                       const float* __restrict__ adst) {
    int n = blockIdx.x;
    int w = threadIdx.x >> 5;
    int l = threadIdx.x & 31;
    const float* hp = hmat + (long)n * D1 + w * F2C;
    float v1 = hp[l], v2 = hp[l + 32];
    float s = v1 * asrc[w * F2C + l] + v2 * asrc[w * F2C + l + 32];
    float d = v1 * adst[w * F2C + l] + v2 * adst[w * F2C + l + 32];
#pragma unroll
    for (int o = 16; o > 0; o >>= 1) {
        s += __shfl_down_sync(0xffffffffu, s, o);
        d += __shfl_down_sync(0xffffffffu, d, o);
    }
    if (l == 0) {
        g_as[n * HC + w] = s;
        g_ad[n * HC + w] = d;
    }
}

// ---------------- per (node,head) online softmax stats -----------------------
__global__ void k_stats() {
    int idx = blockIdx.x * blockDim.x + threadIdx.x;
    if (idx >= NN * HC) return;
    int n = idx >> 3, h = idx & 7;
    float adn = g_ad[idx];
    int beg = g_offs[n], end = g_offs[n + 1];
    // deg >= 1 guaranteed (self loop)
    int src = g_csrc[beg];
    float e = g_as[src * HC + h] + adn;
    e = (e > 0.f) ? e : 0.2f * e;
    float mx = e, s = 1.0f;
    for (int j = beg + 1; j < end; j++) {
        src = g_csrc[j];
        e = g_as[src * HC + h] + adn;
        e = (e > 0.f) ? e : 0.2f * e;
        if (e > mx) { s *= __expf(mx - e); mx = e; }
        s += __expf(e - mx);
    }
    g_m[idx] = mx;
    g_den[idx] = s;
}

// ---------------- heavy aggregation: out[n,:] = sum_e alpha * h[src,:] + bias
// one block (128 thr) per node; thread t owns float4 at feature 4t, head = t>>4
__global__ __launch_bounds__(128) void k_aggregate(const float* __restrict__ hsrc,
                                                   const float* __restrict__ bias,
                                                   float* __restrict__ out) {
    int n = blockIdx.x;
    int t = threadIdx.x;
    int h = t >> 4;
    float adn = g_ad[n * HC + h];
    float mn  = g_m[n * HC + h];
    float inv = 1.0f / (g_den[n * HC + h] + 1e-16f);
    int beg = g_offs[n], end = g_offs[n + 1];
    float4 acc = make_float4(0.f, 0.f, 0.f, 0.f);
    for (int j = beg; j < end; j++) {
        int s = g_csrc[j];
        float e = g_as[s * HC + h] + adn;
        e = (e > 0.f) ? e : 0.2f * e;
        float alpha = __expf(e - mn) * inv;
        float4 v = *(const float4*)&hsrc[(long)s * D1 + t * 4];
        acc.x += alpha * v.x;
        acc.y += alpha * v.y;
        acc.z += alpha * v.z;
        acc.w += alpha * v.w;
    }
    float4 b = *(const float4*)&bias[t * 4];
    acc.x += b.x; acc.y += b.y; acc.z += b.z; acc.w += b.w;
    *(float4*)&out[(long)n * D1 + t * 4] = acc;
}

// ---------------- LSTM elementwise + relu ------------------------------------
__global__ void k_lstm(const float* __restrict__ b_ih, const float* __restrict__ b_hh) {
    int idx = blockIdx.x * blockDim.x + threadIdx.x;
    if (idx >= NN * F2C) return;
    int n = idx >> 6, j = idx & 63;
    const float* g = g_gates + (long)n * G4;
    float i_ = g[j]         + b_ih[j]         + b_hh[j];
    float gg = g[128 + j]   + b_ih[128 + j]   + b_hh[128 + j];
    float o_ = g[192 + j]   + b_ih[192 + j]   + b_hh[192 + j];
    float c  = sigf(i_) * tanhf(gg);
    float hh = sigf(o_) * tanhf(c);
    g_h2[idx] = fmaxf(hh, 0.0f);
}

// ---------------- row softmax over 512 ---------------------------------------
__global__ __launch_bounds__(256) void k_softmax(const float* __restrict__ in,
                                                 float* __restrict__ out) {
    __shared__ float red[256];
    int n = blockIdx.x, t = threadIdx.x;
    float a = in[(long)n * D1 + t];
    float b = in[(long)n * D1 + 256 + t];
    red[t] = fmaxf(a, b);
    __syncthreads();
#pragma unroll
    for (int o = 128; o > 0; o >>= 1) {
        if (t < o) red[t] = fmaxf(red[t], red[t + o]);
        __syncthreads();
    }
    float mx = red[0];
    __syncthreads();
    float ea = __expf(a - mx), eb = __expf(b - mx);
    red[t] = ea + eb;
    __syncthreads();
#pragma unroll
    for (int o = 128; o > 0; o >>= 1) {
        if (t < o) red[t] += red[t + o];
        __syncthreads();
    }
    float inv = 1.0f / red[0];
    out[(long)n * D1 + t] = ea * inv;
    out[(long)n * D1 + 256 + t] = eb * inv;
}

// ---------------- launch -----------------------------------------------------
extern "C" void kernel_launch(void* const* d_in, const int* in_sizes, int n_in,
                              void* d_out, int out_size) {
    const float* x        = (const float*)d_in[0];
    const int*   ei       = (const int*)d_in[1];
    // d_in[2] edge_weight: unused (matches reference)
    const float* W1       = (const float*)d_in[3];
    const float* att_src1 = (const float*)d_in[4];
    const float* att_dst1 = (const float*)d_in[5];
    const float* bias1    = (const float*)d_in[6];
    const float* W_ih     = (const float*)d_in[7];
    // d_in[8] W_hh: unused (h0 = 0)
    const float* b_ih     = (const float*)d_in[9];
    const float* b_hh     = (const float*)d_in[10];
    const float* W2       = (const float*)d_in[11];
    const float* att_src2 = (const float*)d_in[12];
    const float* att_dst2 = (const float*)d_in[13];
    const float* bias2    = (const float*)d_in[14];
    float* out = (float*)d_out;

    int E = in_sizes[1] / 2;

    void* p_deg = nullptr;
    cudaGetSymbolAddress(&p_deg, g_deg);
    void* p_h1 = nullptr;    cudaGetSymbolAddress(&p_h1, g_h1);
    void* p_agg1 = nullptr;  cudaGetSymbolAddress(&p_agg1, g_agg1);
    void* p_gates = nullptr; cudaGetSymbolAddress(&p_gates, g_gates);
    void* p_h2 = nullptr;    cudaGetSymbolAddress(&p_h2, g_h2);
    void* p_h3 = nullptr;    cudaGetSymbolAddress(&p_h3, g_h3);
    void* p_agg2 = nullptr;  cudaGetSymbolAddress(&p_agg2, g_agg2);
    void* p_wiht = nullptr;  cudaGetSymbolAddress(&p_wiht, g_Wiht);

    // CSR build
    cudaMemsetAsync(p_deg, 0, NN * sizeof(int), 0);
    int etot = E + NN;
    k_degree<<<(etot + 255) / 256, 256>>>(ei, E);
    k_scan<<<1, 1024>>>();
    k_scatter<<<(etot + 255) / 256, 256>>>(ei, E);
    k_transpose<<<(G4 * D1 + 255) / 256, 256>>>(W_ih);

    dim3 gemmBlk(256);
    // GAT layer 1
    {
        dim3 grid(D1 / BN, (NN + BM - 1) / BM);
        k_sgemm<<<grid, gemmBlk>>>(NN, D1, FIN, x, W1, (float*)p_h1);
    }
    k_attn<<<NN, 256>>>((const float*)p_h1, att_src1, att_dst1);
    k_stats<<<(NN * HC + 255) / 256, 256>>>();
    k_aggregate<<<NN, 128>>>((const float*)p_h1, bias1, (float*)p_agg1);

    // LSTM
    {
        dim3 grid(G4 / BN, (NN + BM - 1) / BM);
        k_sgemm<<<grid, gemmBlk>>>(NN, G4, D1, (const float*)p_agg1,
                                   (const float*)p_wiht, (float*)p_gates);
    }
    k_lstm<<<(NN * F2C + 255) / 256, 256>>>(b_ih, b_hh);

    // GAT layer 2
    {
        dim3 grid(D1 / BN, (NN + BM - 1) / BM);
        k_sgemm<<<grid, gemmBlk>>>(NN, D1, F2C, (const float*)p_h2, W2, (float*)p_h3);
    }
    k_attn<<<NN, 256>>>((const float*)p_h3, att_src2, att_dst2);
    k_stats<<<(NN * HC + 255) / 256, 256>>>();
    k_aggregate<<<NN, 128>>>((const float*)p_h3, bias2, (float*)p_agg2);

    // softmax
    k_softmax<<<NN, 256>>>((const float*)p_agg2, out);
}

// round 2
// speedup vs baseline: 1.5703x; 1.5703x over previous
#include <cuda_runtime.h>
#include <cuda_bf16.h>
#include <math.h>

#define NN 20000
#define EE 320000
#define ET (EE + NN)       // 340000 edges incl self loops
#define FIN 128
#define F2C 64
#define HC 8
#define D1 512             // H*F2
#define G4 256             // 4*F2

// ---------------- scratch (device globals; no allocation allowed) ------------
__device__ float g_h1[NN * D1];        // x @ W1
__device__ float g_agg1[NN * D1];      // GAT1 output
__device__ float g_gates[NN * G4];     // LSTM gates
__device__ float g_h2[NN * F2C];       // LSTM out (relu'd)
__device__ float g_h3[NN * D1];        // h2 @ W2
__device__ float g_agg2[NN * D1];      // GAT2 output (pre-softmax)
__device__ float g_as[NN * HC];
__device__ float g_ad[NN * HC];
__device__ float g_m[NN * HC];
__device__ float g_den[NN * HC];
__device__ float g_Wiht[D1 * G4];      // W_ih transposed -> [512,256]
__device__ int   g_deg[NN];
__device__ int   g_offs[NN + 1];
__device__ int   g_cur[NN];
__device__ int   g_csrc[ET];

__device__ __forceinline__ float sigf(float x) { return 1.0f / (1.0f + __expf(-x)); }

__device__ __forceinline__ unsigned f2tf(float f) {
    unsigned u;
    asm("cvt.rna.tf32.f32 %0, %1;" : "=r"(u) : "f"(f));
    return u;
}

// ---------------- CSR build -------------------------------------------------
__global__ void k_degree(const int* __restrict__ ei, int E) {
    int i = blockIdx.x * blockDim.x + threadIdx.x;
    if (i >= E + NN) return;
    int dst = (i < E) ? ei[E + i] : (i - E);
    atomicAdd(&g_deg[dst], 1);
}

__global__ void k_scan() {
    __shared__ int sums[1024];
    const int CH = 20;                       // 1024*20 = 20480 >= NN
    int t = threadIdx.x;
    int b = t * CH;
    int e = min(b + CH, NN);
    int tmp[CH];
    int local = 0;
    for (int i = b; i < e; i++) { tmp[i - b] = g_deg[i]; local += tmp[i - b]; }
    sums[t] = local;
    __syncthreads();
    for (int o = 1; o < 1024; o <<= 1) {
        int v = (t >= o) ? sums[t - o] : 0;
        __syncthreads();
        sums[t] += v;
        __syncthreads();
    }
    int run = sums[t] - local;               // exclusive prefix
    for (int i = b; i < e; i++) {
        g_offs[i] = run;
        g_cur[i]  = run;
        run += tmp[i - b];
    }
    if (b < NN && e == NN) g_offs[NN] = run;
}

__global__ void k_scatter(const int* __restrict__ ei, int E) {
    int i = blockIdx.x * blockDim.x + threadIdx.x;
    if (i >= E + NN) return;
    int src, dst;
    if (i < E) { src = ei[i]; dst = ei[E + i]; }
    else       { src = dst = i - E; }
    int pos = atomicAdd(&g_cur[dst], 1);
    g_csrc[pos] = src;
}

// ---------------- W_ih transpose --------------------------------------------
__global__ void k_transpose(const float* __restrict__ Wih) {
    int idx = blockIdx.x * blockDim.x + threadIdx.x;
    if (idx >= G4 * D1) return;
    int j = idx >> 9;          // 0..255
    int k = idx & 511;         // 0..511
    g_Wiht[k * G4 + j] = Wih[idx];
}

// ---------------- TF32 tensor-core GEMM: C[M,N] = A[M,K] @ B[K,N] ------------
// 128x128 block tile, BK=16, 8 warps (4x2), warp tile 32x64 via m16n8k8.
// Requires: N % 128 == 0, K % 16 == 0. M guarded.
__global__ __launch_bounds__(256) void k_tfgemm(int M, int N, int K,
                                                const float* __restrict__ A,
                                                const float* __restrict__ B,
                                                float* __restrict__ C) {
    __shared__ unsigned As[16][136];   // [k][m], stride 136 -> bank = (8k+m)%32 unique
    __shared__ unsigned Bs[16][136];   // [k][n]
    int tid  = threadIdx.x;
    int lane = tid & 31;
    int warp = tid >> 5;
    int wr = warp & 3;                 // warp row 0..3 (32 rows each)
    int wc = warp >> 2;                // warp col 0..1 (64 cols each)
    int blockRow = blockIdx.y * 128;
    int blockCol = blockIdx.x * 128;

    float acc[2][8][4];
#pragma unroll
    for (int i = 0; i < 2; i++)
#pragma unroll
        for (int j = 0; j < 8; j++)
#pragma unroll
            for (int q = 0; q < 4; q++) acc[i][j][q] = 0.0f;

    int arow = tid >> 2;               // 0..63
    int acol = (tid & 3) * 4;          // 0,4,8,12
    int brow = tid >> 5;               // 0..7
    int bcol = (tid & 31) * 4;         // 0..124

    for (int k0 = 0; k0 < K; k0 += 16) {
        // stage A tile (128 x 16), transpose to [k][m], convert to tf32
#pragma unroll
        for (int half = 0; half < 2; half++) {
            int r = arow + half * 64;
            float4 v = make_float4(0.f, 0.f, 0.f, 0.f);
            if (blockRow + r < M)
                v = *(const float4*)&A[(long)(blockRow + r) * K + k0 + acol];
            As[acol + 0][r] = f2tf(v.x);
            As[acol + 1][r] = f2tf(v.y);
            As[acol + 2][r] = f2tf(v.z);
            As[acol + 3][r] = f2tf(v.w);
        }
        // stage B tile (16 x 128)
#pragma unroll
        for (int half = 0; half < 2; half++) {
            int kr = brow + half * 8;
            float4 v = *(const float4*)&B[(long)(k0 + kr) * N + blockCol + bcol];
            uint4 u = make_uint4(f2tf(v.x), f2tf(v.y), f2tf(v.z), f2tf(v.w));
            *(uint4*)&Bs[kr][bcol] = u;
        }
        __syncthreads();

#pragma unroll
        for (int ks = 0; ks < 16; ks += 8) {
            unsigned a[2][4], b[8][2];
            int r0 = wr * 32 + (lane >> 2);
            int c0 = ks + (lane & 3);
#pragma unroll
            for (int i = 0; i < 2; i++) {
                a[i][0] = As[c0][r0 + i * 16];
                a[i][1] = As[c0][r0 + i * 16 + 8];
                a[i][2] = As[c0 + 4][r0 + i * 16];
                a[i][3] = As[c0 + 4][r0 + i * 16 + 8];
            }
            int bn = wc * 64 + (lane >> 2);
#pragma unroll
            for (int j = 0; j < 8; j++) {
                b[j][0] = Bs[c0][bn + j * 8];
                b[j][1] = Bs[c0 + 4][bn + j * 8];
            }
#pragma unroll
            for (int i = 0; i < 2; i++) {
#pragma unroll
                for (int j = 0; j < 8; j++) {
                    asm volatile(
                        "mma.sync.aligned.m16n8k8.row.col.f32.tf32.tf32.f32 "
                        "{%0,%1,%2,%3}, {%4,%5,%6,%7}, {%8,%9}, {%0,%1,%2,%3};"
                        : "+f"(acc[i][j][0]), "+f"(acc[i][j][1]),
                          "+f"(acc[i][j][2]), "+f"(acc[i][j][3])
                        : "r"(a[i][0]), "r"(a[i][1]), "r"(a[i][2]), "r"(a[i][3]),
                          "r"(b[j][0]), "r"(b[j][1]));
                }
            }
        }
        __syncthreads();
    }

    // store C
#pragma unroll
    for (int i = 0; i < 2; i++) {
        int r = blockRow + wr * 32 + i * 16 + (lane >> 2);
#pragma unroll
        for (int j = 0; j < 8; j++) {
            int c = blockCol + wc * 64 + j * 8 + (lane & 3) * 2;
            if (r < M)
                *(float2*)&C[(long)r * N + c] = make_float2(acc[i][j][0], acc[i][j][1]);
            if (r + 8 < M)
                *(float2*)&C[(long)(r + 8) * N + c] = make_float2(acc[i][j][2], acc[i][j][3]);
        }
    }
}

// ---------------- attention dots: a_s[n,h], a_d[n,h] -------------------------
__global__ void k_attn(const float* __restrict__ hmat,
                       const float* __restrict__ asrc,
                       const float* __restrict__ adst) {
    int n = blockIdx.x;
    int w = threadIdx.x >> 5;
    int l = threadIdx.x & 31;
    const float* hp = hmat + (long)n * D1 + w * F2C;
    float v1 = hp[l], v2 = hp[l + 32];
    float s = v1 * asrc[w * F2C + l] + v2 * asrc[w * F2C + l + 32];
    float d = v1 * adst[w * F2C + l] + v2 * adst[w * F2C + l + 32];
#pragma unroll
    for (int o = 16; o > 0; o >>= 1) {
        s += __shfl_down_sync(0xffffffffu, s, o);
        d += __shfl_down_sync(0xffffffffu, d, o);
    }
    if (l == 0) {
        g_as[n * HC + w] = s;
        g_ad[n * HC + w] = d;
    }
}

// ---------------- per (node,head) online softmax stats -----------------------
__global__ void k_stats() {
    int idx = blockIdx.x * blockDim.x + threadIdx.x;
    if (idx >= NN * HC) return;
    int n = idx >> 3, h = idx & 7;
    float adn = g_ad[idx];
    int beg = g_offs[n], end = g_offs[n + 1];
    int src = g_csrc[beg];
    float e = g_as[src * HC + h] + adn;
    e = (e > 0.f) ? e : 0.2f * e;
    float mx = e, s = 1.0f;
    for (int j = beg + 1; j < end; j++) {
        src = g_csrc[j];
        e = g_as[src * HC + h] + adn;
        e = (e > 0.f) ? e : 0.2f * e;
        if (e > mx) { s *= __expf(mx - e); mx = e; }
        s += __expf(e - mx);
    }
    g_m[idx] = mx;
    g_den[idx] = s;
}

// ---------------- heavy aggregation ------------------------------------------
__global__ __launch_bounds__(128) void k_aggregate(const float* __restrict__ hsrc,
                                                   const float* __restrict__ bias,
                                                   float* __restrict__ out) {
    int n = blockIdx.x;
    int t = threadIdx.x;
    int h = t >> 4;
    float adn = g_ad[n * HC + h];
    float mn  = g_m[n * HC + h];
    float inv = 1.0f / (g_den[n * HC + h] + 1e-16f);
    int beg = g_offs[n], end = g_offs[n + 1];
    float4 acc = make_float4(0.f, 0.f, 0.f, 0.f);
    for (int j = beg; j < end; j++) {
        int s = g_csrc[j];
        float e = g_as[s * HC + h] + adn;
        e = (e > 0.f) ? e : 0.2f * e;
        float alpha = __expf(e - mn) * inv;
        float4 v = *(const float4*)&hsrc[(long)s * D1 + t * 4];
        acc.x += alpha * v.x;
        acc.y += alpha * v.y;
        acc.z += alpha * v.z;
        acc.w += alpha * v.w;
    }
    float4 b = *(const float4*)&bias[t * 4];
    acc.x += b.x; acc.y += b.y; acc.z += b.z; acc.w += b.w;
    *(float4*)&out[(long)n * D1 + t * 4] = acc;
}

// ---------------- LSTM elementwise + relu ------------------------------------
__global__ void k_lstm(const float* __restrict__ b_ih, const float* __restrict__ b_hh) {
    int idx = blockIdx.x * blockDim.x + threadIdx.x;
    if (idx >= NN * F2C) return;
    int n = idx >> 6, j = idx & 63;
    const float* g = g_gates + (long)n * G4;
    float i_ = g[j]         + b_ih[j]         + b_hh[j];
    float gg = g[128 + j]   + b_ih[128 + j]   + b_hh[128 + j];
    float o_ = g[192 + j]   + b_ih[192 + j]   + b_hh[192 + j];
    float c  = sigf(i_) * tanhf(gg);
    float hh = sigf(o_) * tanhf(c);
    g_h2[idx] = fmaxf(hh, 0.0f);
}

// ---------------- row softmax over 512 ---------------------------------------
__global__ __launch_bounds__(256) void k_softmax(const float* __restrict__ in,
                                                 float* __restrict__ out) {
    __shared__ float red[256];
    int n = blockIdx.x, t = threadIdx.x;
    float a = in[(long)n * D1 + t];
    float b = in[(long)n * D1 + 256 + t];
    red[t] = fmaxf(a, b);
    __syncthreads();
#pragma unroll
    for (int o = 128; o > 0; o >>= 1) {
        if (t < o) red[t] = fmaxf(red[t], red[t + o]);
        __syncthreads();
    }
    float mx = red[0];
    __syncthreads();
    float ea = __expf(a - mx), eb = __expf(b - mx);
    red[t] = ea + eb;
    __syncthreads();
#pragma unroll
    for (int o = 128; o > 0; o >>= 1) {
        if (t < o) red[t] += red[t + o];
        __syncthreads();
    }
    float inv = 1.0f / red[0];
    out[(long)n * D1 + t] = ea * inv;
    out[(long)n * D1 + 256 + t] = eb * inv;
}

// ---------------- launch -----------------------------------------------------
extern "C" void kernel_launch(void* const* d_in, const int* in_sizes, int n_in,
                              void* d_out, int out_size) {
    const float* x        = (const float*)d_in[0];
    const int*   ei       = (const int*)d_in[1];
    // d_in[2] edge_weight: unused (matches reference)
    const float* W1       = (const float*)d_in[3];
    const float* att_src1 = (const float*)d_in[4];
    const float* att_dst1 = (const float*)d_in[5];
    const float* bias1    = (const float*)d_in[6];
    const float* W_ih     = (const float*)d_in[7];
    // d_in[8] W_hh: unused (h0 = 0)
    const float* b_ih     = (const float*)d_in[9];
    const float* b_hh     = (const float*)d_in[10];
    const float* W2       = (const float*)d_in[11];
    const float* att_src2 = (const float*)d_in[12];
    const float* att_dst2 = (const float*)d_in[13];
    const float* bias2    = (const float*)d_in[14];
    float* out = (float*)d_out;

    int E = in_sizes[1] / 2;

    void* p_deg = nullptr;   cudaGetSymbolAddress(&p_deg, g_deg);
    void* p_h1 = nullptr;    cudaGetSymbolAddress(&p_h1, g_h1);
    void* p_agg1 = nullptr;  cudaGetSymbolAddress(&p_agg1, g_agg1);
    void* p_gates = nullptr; cudaGetSymbolAddress(&p_gates, g_gates);
    void* p_h2 = nullptr;    cudaGetSymbolAddress(&p_h2, g_h2);
    void* p_h3 = nullptr;    cudaGetSymbolAddress(&p_h3, g_h3);
    void* p_agg2 = nullptr;  cudaGetSymbolAddress(&p_agg2, g_agg2);
    void* p_wiht = nullptr;  cudaGetSymbolAddress(&p_wiht, g_Wiht);

    // CSR build
    cudaMemsetAsync(p_deg, 0, NN * sizeof(int), 0);
    int etot = E + NN;
    k_degree<<<(etot + 255) / 256, 256>>>(ei, E);
    k_scan<<<1, 1024>>>();
    k_scatter<<<(etot + 255) / 256, 256>>>(ei, E);
    k_transpose<<<(G4 * D1 + 255) / 256, 256>>>(W_ih);

    dim3 gemmBlk(256);
    int gridM = (NN + 127) / 128;

    // GAT layer 1: h1 = x @ W1   [20000,128]@[128,512]
    {
        dim3 grid(D1 / 128, gridM);
        k_tfgemm<<<grid, gemmBlk>>>(NN, D1, FIN, x, W1, (float*)p_h1);
    }
    k_attn<<<NN, 256>>>((const float*)p_h1, att_src1, att_dst1);
    k_stats<<<(NN * HC + 255) / 256, 256>>>();
    k_aggregate<<<NN, 128>>>((const float*)p_h1, bias1, (float*)p_agg1);

    // LSTM: gates = agg1 @ W_ih^T   [20000,512]@[512,256]
    {
        dim3 grid(G4 / 128, gridM);
        k_tfgemm<<<grid, gemmBlk>>>(NN, G4, D1, (const float*)p_agg1,
                                    (const float*)p_wiht, (float*)p_gates);
    }
    k_lstm<<<(NN * F2C + 255) / 256, 256>>>(b_ih, b_hh);

    // GAT layer 2: h3 = h2 @ W2   [20000,64]@[64,512]
    {
        dim3 grid(D1 / 128, gridM);
        k_tfgemm<<<grid, gemmBlk>>>(NN, D1, F2C, (const float*)p_h2, W2, (float*)p_h3);
    }
    k_attn<<<NN, 256>>>((const float*)p_h3, att_src2, att_dst2);
    k_stats<<<(NN * HC + 255) / 256, 256>>>();
    k_aggregate<<<NN, 128>>>((const float*)p_h3, bias2, (float*)p_agg2);

    // softmax
    k_softmax<<<NN, 256>>>((const float*)p_agg2, out);
}